// round 16
// baseline (speedup 1.0000x reference)
#include <cuda_runtime.h>
#include <cuda_fp16.h>
#include <math.h>
#include <stdint.h>

#define BB   4
#define NN   16384
#define CIN  128
#define COUT 256
#define HH   256
#define WW   256
#define NP   65536      // N0 = H*W points
#define HD   128
#define WD   128
#define HC   64
#define WC   64
#define NS   4096       // HC*WC
#define EPSV 1e-6f
#define KTOT 1152       // 9*CIN
#define SLABS 36        // KTOT/32

// ---------------- scratch (device globals: no allocation allowed) ----------------
__device__ float  g_cnt [(size_t)BB*HH*WW];       // token2map count
__device__ uint2  g_mapH[(size_t)BB*HH*WW*CIN/4]; // fp16 map: accum then normalized (64MB)
__device__ __half g_yH  [(size_t)BB*HD*WD*COUT];  // conv output fp16 (32MB)
__device__ uint2  g_xH  [(size_t)BB*NN*CIN/4];    // x in fp16 (16MB)
__device__ __half g_numH[(size_t)BB*NN*COUT];     // map2token accum -> tok, fp16 (32MB)
__device__ float  g_den [(size_t)BB*NN];
__device__ float  g_wexp[(size_t)BB*NN];          // exp(conf)
__device__ float  g_bnsumF[COUT];
__device__ float  g_bnsqF [COUT];
__device__ float  g_scale[COUT];
__device__ float  g_shift[COUT];
__device__ float  g_cnum[(size_t)BB*NS*COUT];     // cluster num (16MB)
__device__ float  g_cden[(size_t)BB*NS];
__device__ float  g_wpt [(size_t)BB*NP];          // per-point weight, reused
__device__ unsigned g_maxw[BB];
__device__ uint2  g_wBh [(size_t)SLABS*2048];     // conv weights fp16 frag image per slab
__device__ uint2  g_wSh [(size_t)4*2048];         // skip weights fp16 frag image (4 slabs)

// ---------------- helpers ----------------
__device__ __forceinline__ void red_add4(float* p, float4 v) {
    asm volatile("red.global.add.v4.f32 [%0], {%1,%2,%3,%4};"
                 :: "l"(__cvta_generic_to_global(p)),
                    "f"(v.x), "f"(v.y), "f"(v.z), "f"(v.w) : "memory");
}

__device__ __forceinline__ int grid_cell(float lx, float ly, int Hg, int Wg) {
    lx = fminf(fmaxf(lx, -1.f), 1.f);
    ly = fminf(fmaxf(ly, -1.f), 1.f);
    int px = min(max(__float2int_rn(0.5f*(lx+1.f)*(float)Wg - 0.5f), 0), Wg-1);
    int py = min(max(__float2int_rn(0.5f*(ly+1.f)*(float)Hg - 0.5f), 0), Hg-1);
    return py*Wg + px;
}

__device__ __forceinline__ uint32_t packh2(float lo, float hi) {
    __half2 h = __floats2half2_rn(lo, hi);
    return *(uint32_t*)&h;
}

__device__ __forceinline__ uint32_t smem_u32(const void* p) {
    uint32_t a;
    asm("{ .reg .u64 t; cvta.to.shared.u64 t, %1; cvt.u32.u64 %0, t; }" : "=r"(a) : "l"(p));
    return a;
}

__device__ __forceinline__ void cpa16(uint32_t dst, const void* src, int srcsz) {
    asm volatile("cp.async.cg.shared.global [%0], [%1], 16, %2;"
                 :: "r"(dst), "l"(__cvta_generic_to_global(src)), "r"(srcsz) : "memory");
}

__device__ __forceinline__ void mma16(float& d0, float& d1, float& d2, float& d3,
                                      uint32_t a0, uint32_t a1, uint32_t a2, uint32_t a3,
                                      uint32_t b0, uint32_t b1) {
    asm volatile("mma.sync.aligned.m16n8k16.row.col.f32.f16.f16.f32 "
                 "{%0,%1,%2,%3},{%4,%5,%6,%7},{%8,%9},{%0,%1,%2,%3};"
                 : "+f"(d0), "+f"(d1), "+f"(d2), "+f"(d3)
                 : "r"(a0), "r"(a1), "r"(a2), "r"(a3), "r"(b0), "r"(b1));
}

__device__ __forceinline__ int aswz(int r, int c) {      // 16B-chunk swizzle
    return c ^ (r & 3) ^ ((r >> 2) & 1);
}
__device__ __forceinline__ uint32_t a_word(const char* sA, int r, int w) {  // w 0..15
    int off = r*64 + aswz(r, w >> 2)*16 + (w & 3)*4;
    return *(const uint32_t*)(sA + off);
}

// ---------------- kernels ----------------
// fused: zero accumulators + fp16 conv/skip B images + fp16 copy of x
__global__ void k_init(const float* __restrict__ x, const float* __restrict__ skw,
                       const float* __restrict__ cw) {
    size_t t = (size_t)blockIdx.x*blockDim.x + threadIdx.x;
    size_t stride = (size_t)gridDim.x*blockDim.x;
    float4 z = make_float4(0.f,0.f,0.f,0.f);
    for (size_t i=t; i < (size_t)BB*HH*WW*CIN/8; i+=stride) ((float4*)g_mapH)[i]=z;
    for (size_t i=t; i < (size_t)BB*HH*WW/4;     i+=stride) ((float4*)g_cnt )[i]=z;
    for (size_t i=t; i < (size_t)BB*NN*COUT/8;   i+=stride) ((float4*)g_numH)[i]=z;
    for (size_t i=t; i < (size_t)BB*NN/4;        i+=stride) ((float4*)g_den )[i]=z;
    for (size_t i=t; i < (size_t)BB*NS*COUT/4;   i+=stride) ((float4*)g_cnum)[i]=z;
    for (size_t i=t; i < (size_t)BB*NS/4;        i+=stride) ((float4*)g_cden)[i]=z;
    for (size_t i=t; i < (size_t)BB*NN*CIN/4;    i+=stride) {
        float4 v = ((const float4*)x)[i];
        uint2 h; h.x = packh2(v.x, v.y); h.y = packh2(v.z, v.w);
        g_xH[i] = h;
    }
    if (t < COUT) { g_bnsumF[t]=0.f; g_bnsqF[t]=0.f; }
    if (t < BB)   g_maxw[t]=0u;
    if (t < (size_t)SLABS*2048) {
        int fi = (int)t;
        int s   = fi >> 11, r = fi & 2047;
        int nh  = r >> 10;  int r2 = r & 1023;
        int ntF = r2 >> 6, h16 = (r2 >> 5) & 1, g = (r2 >> 2) & 7, cl = r2 & 3;
        int n   = nh*128 + ntF*8 + g;
        int k0  = s*32 + h16*16 + 2*cl;
        uint2 v;
        v.x = packh2(cw[(size_t)k0*COUT + n],     cw[(size_t)(k0+1)*COUT + n]);
        v.y = packh2(cw[(size_t)(k0+8)*COUT + n], cw[(size_t)(k0+9)*COUT + n]);
        g_wBh[fi] = v;
    }
    if (t < (size_t)4*2048) {
        int fi = (int)t;
        int s   = fi >> 11, r = fi & 2047;
        int nh  = r >> 10;  int r2 = r & 1023;
        int ntF = r2 >> 6, h16 = (r2 >> 5) & 1, g = (r2 >> 2) & 7, cl = r2 & 3;
        int n   = nh*128 + ntF*8 + g;
        int k0  = s*32 + h16*16 + 2*cl;
        const float* wr = skw + (size_t)n*CIN;     // skip_w[n][k]
        uint2 v;
        v.x = packh2(wr[k0],   wr[k0+1]);
        v.y = packh2(wr[k0+8], wr[k0+9]);
        g_wSh[fi] = v;
    }
}

// scatter fp16 token features into fp16 map (sum via f16x2 atomics + count)
__global__ void k_token2map(const float* __restrict__ loc, const int* __restrict__ idx_agg) {
    int p    = blockIdx.x*8 + (threadIdx.x>>5);
    int lane = threadIdx.x & 31;
    int b    = p >> 16;
    float lx = loc[2*p], ly = loc[2*p+1];
    int cell = grid_cell(lx, ly, HH, WW);
    int i    = idx_agg[p];
    uint2 v = g_xH[((size_t)b*NN + i)*CIN/4 + lane];
    __half2* dst = (__half2*)((__half*)g_mapH + ((size_t)b*HH*WW + cell)*CIN + lane*4);
    atomicAdd(dst,     *(__half2*)&v.x);
    atomicAdd(dst + 1, *(__half2*)&v.y);
    if (!lane) atomicAdd(&g_cnt[(size_t)b*HH*WW + cell], 1.0f);
}

// normalize fp16 map in place
__global__ void k_norm() {
    size_t i = (size_t)blockIdx.x*256 + threadIdx.x;
    float rcp = 1.f/(g_cnt[i >> 5] + EPSV);
    uint2 h = g_mapH[i];
    float2 a = __half22float2(*(__half2*)&h.x);
    float2 c = __half22float2(*(__half2*)&h.y);
    uint2 o;
    o.x = packh2(a.x*rcp, a.y*rcp);
    o.y = packh2(c.x*rcp, c.y*rcp);
    g_mapH[i] = o;
}

// ---- 3x3 stride-2 conv as implicit GEMM on mma.sync FP16 (m16n8k16) ----
#define CV_BUF   16384
#define CV_A(i)  ((i)*CV_BUF)
#define CV_B(i)  ((i)*CV_BUF + 8192)
#define CV_BIAS  (3*CV_BUF)
#define CV_SMEM  (CV_BIAS + 1024)

__global__ void __launch_bounds__(256, 2) k_conv(const float* __restrict__ cb) {
    extern __shared__ char smem[];
    uint32_t sb = smem_u32(smem);
    int tid = threadIdx.x, w = tid >> 5, lane = tid & 31;
    int g = lane >> 2, cl = lane & 3;
    int wm = w & 3, wn = w >> 2;                 // warp tile 32m x 64n
    int oy = blockIdx.x, nh = blockIdx.y, b = blockIdx.z;

    if (tid < 128) *(float*)(smem + CV_BIAS + tid*4) = cb[nh*128 + tid];

    float acc[2][8][4];
    #pragma unroll
    for (int mt=0;mt<2;mt++) for (int nt=0;nt<8;nt++) for (int r2=0;r2<4;r2++) acc[mt][nt][r2]=0.f;

    auto stage = [&](int s, int buf) {
        int tap = s >> 2, cinb = (s & 3) * 32;
        int ky = tap / 3, kx = tap - 3*ky;
        int iy = 2*oy - 1 + ky;
        bool iyok = (unsigned)iy < HH;
        int r = tid >> 1, c0 = (tid & 1) * 2;
        int ix = 2*r - 1 + kx;
        bool ok = iyok && ((unsigned)ix < WW);
        const __half* src = (const __half*)g_mapH
            + ((size_t)b*HH*WW + (size_t)(iyok ? iy : 0)*WW + (ok ? ix : 0))*CIN + cinb;
        uint32_t dstA = sb + CV_A(buf) + r*64;
        int sz = ok ? 16 : 0;
        #pragma unroll
        for (int j = 0; j < 2; j++) {
            int c = c0 + j;
            cpa16(dstA + aswz(r, c)*16, src + c*8, sz);
        }
        const uint2* bsrc = g_wBh + (size_t)s*2048 + nh*1024 + tid*4;
        uint32_t dstB = sb + CV_B(buf) + tid*32;
        cpa16(dstB,      bsrc,     16);
        cpa16(dstB + 16, bsrc + 2, 16);
        asm volatile("cp.async.commit_group;" ::: "memory");
    };

    stage(0, 0);
    stage(1, 1);

    int bufc = 0;
    for (int s = 0; s < SLABS; s++) {
        if (s < SLABS-1) asm volatile("cp.async.wait_group 1;" ::: "memory");
        else             asm volatile("cp.async.wait_group 0;" ::: "memory");
        __syncthreads();
        int bufn = bufc + 2; if (bufn >= 3) bufn -= 3;
        if (s + 2 < SLABS) stage(s + 2, bufn);
        const char*  sA = smem + CV_A(bufc);
        const uint2* sB = (const uint2*)(smem + CV_B(bufc));
        #pragma unroll
        for (int h16 = 0; h16 < 2; h16++) {
            uint2 bv[8];
            #pragma unroll
            for (int nt = 0; nt < 8; nt++)
                bv[nt] = sB[(wn*8 + nt)*64 + h16*32 + g*4 + cl];
            uint32_t a[2][4];
            #pragma unroll
            for (int mt = 0; mt < 2; mt++) {
                int r0 = wm*32 + mt*16 + g;
                a[mt][0] = a_word(sA, r0,     h16*8 + cl);
                a[mt][1] = a_word(sA, r0 + 8, h16*8 + cl);
                a[mt][2] = a_word(sA, r0,     h16*8 + cl + 4);
                a[mt][3] = a_word(sA, r0 + 8, h16*8 + cl + 4);
            }
            #pragma unroll
            for (int mt = 0; mt < 2; mt++)
                #pragma unroll
                for (int nt = 0; nt < 8; nt++)
                    mma16(acc[mt][nt][0], acc[mt][nt][1], acc[mt][nt][2], acc[mt][nt][3],
                          a[mt][0], a[mt][1], a[mt][2], a[mt][3],
                          bv[nt].x, bv[nt].y);
        }
        bufc++; if (bufc >= 3) bufc = 0;
    }

    // epilogue: write fp16 y
    const float* bias = (const float*)(smem + CV_BIAS);
    __half* ybase = g_yH + (((size_t)b*HD + oy)*WD)*COUT + nh*128;
    #pragma unroll
    for (int mt = 0; mt < 2; mt++) {
        int ox0 = wm*32 + mt*16 + g;
        #pragma unroll
        for (int nt = 0; nt < 8; nt++) {
            int n = wn*64 + nt*8 + cl*2;
            float b0 = bias[n], b1 = bias[n+1];
            *(uint32_t*)(ybase + (size_t)ox0*COUT + n)     = packh2(acc[mt][nt][0]+b0, acc[mt][nt][1]+b1);
            *(uint32_t*)(ybase + (size_t)(ox0+8)*COUT + n) = packh2(acc[mt][nt][2]+b0, acc[mt][nt][3]+b1);
        }
    }
}

// bilinear gather from fp16 conv map at orig points, weighted scatter to fp16 tokens
__global__ void k_map2token(const float* __restrict__ loc, const int* __restrict__ idx_agg,
                            const float* __restrict__ aggw) {
    int p    = blockIdx.x*8 + (threadIdx.x>>5);
    int lane = threadIdx.x & 31;
    int b    = p >> 16;
    float lx = fminf(fmaxf(loc[2*p],   -1.f), 1.f);
    float ly = fminf(fmaxf(loc[2*p+1], -1.f), 1.f);
    float fx = fminf(fmaxf(0.5f*(lx+1.f)*(float)WD - 0.5f, 0.f), (float)(WD-1));
    float fy = fminf(fmaxf(0.5f*(ly+1.f)*(float)HD - 0.5f, 0.f), (float)(HD-1));
    float x0f = floorf(fx), y0f = floorf(fy);
    float wx = fx - x0f, wy = fy - y0f;
    int x0 = (int)x0f, y0 = (int)y0f;
    int x1 = min(x0+1, WD-1), y1 = min(y0+1, HD-1);
    const __half* base = g_yH + (size_t)b*HD*WD*COUT;
    const uint4* r00 = (const uint4*)(base + (size_t)(y0*WD+x0)*COUT);
    const uint4* r01 = (const uint4*)(base + (size_t)(y0*WD+x1)*COUT);
    const uint4* r10 = (const uint4*)(base + (size_t)(y1*WD+x0)*COUT);
    const uint4* r11 = (const uint4*)(base + (size_t)(y1*WD+x1)*COUT);
    float w00=(1.f-wx)*(1.f-wy), w01=wx*(1.f-wy), w10=(1.f-wx)*wy, w11=wx*wy;
    float wpt = aggw[p];
    int i = idx_agg[p];
    __half2* dst = (__half2*)(g_numH + ((size_t)b*NN + i)*COUT + lane*8);
    uint4 ua = r00[lane], ub = r01[lane], uc = r10[lane], ud = r11[lane];
    const uint32_t* pa = (const uint32_t*)&ua;
    const uint32_t* pb = (const uint32_t*)&ub;
    const uint32_t* pc = (const uint32_t*)&uc;
    const uint32_t* pd = (const uint32_t*)&ud;
    #pragma unroll
    for (int q = 0; q < 4; q++) {
        float2 a0 = __half22float2(*(__half2*)&pa[q]);
        float2 b0 = __half22float2(*(__half2*)&pb[q]);
        float2 c0 = __half22float2(*(__half2*)&pc[q]);
        float2 d0 = __half22float2(*(__half2*)&pd[q]);
        float f0 = (w00*a0.x + w01*b0.x + w10*c0.x + w11*d0.x)*wpt;
        float f1 = (w00*a0.y + w01*b0.y + w10*c0.y + w11*d0.y)*wpt;
        uint32_t hv = packh2(f0, f1);
        atomicAdd(dst + q, *(__half2*)&hv);
    }
    if (!lane) atomicAdd(&g_den[(size_t)b*NN + i], wpt);
}

// ---- skip GEMM (x @ skip_w^T) on FP16 mma.sync + fused BN partial stats ----
__global__ void __launch_bounds__(256, 2) k_skip() {
    extern __shared__ char smem[];
    uint32_t sb = smem_u32(smem);
    int tid = threadIdx.x, w = tid >> 5, lane = tid & 31;
    int g = lane >> 2, cl = lane & 3;
    int wm = w & 3, wn = w >> 2;
    int m0 = blockIdx.x * 128, nh = blockIdx.y;
    const __half* xrow = (const __half*)g_xH + (size_t)m0*CIN;
    float* s_sum = (float*)(smem + CV_BIAS);        // [128]
    float* s_sq  = (float*)(smem + CV_BIAS + 512);  // [128]

    if (tid < 256) *(float*)(smem + CV_BIAS + tid*4) = 0.f;

    float acc[2][8][4];
    #pragma unroll
    for (int mt=0;mt<2;mt++) for (int nt=0;nt<8;nt++) for (int r2=0;r2<4;r2++) acc[mt][nt][r2]=0.f;

    auto stage = [&](int s, int buf) {
        int r = tid >> 1, c0 = (tid & 1) * 2;
        const __half* src = xrow + (size_t)r*CIN + s*32;
        uint32_t dstA = sb + CV_A(buf) + r*64;
        #pragma unroll
        for (int j = 0; j < 2; j++) {
            int c = c0 + j;
            cpa16(dstA + aswz(r, c)*16, src + c*8, 16);
        }
        const uint2* bsrc = g_wSh + (size_t)s*2048 + nh*1024 + tid*4;
        uint32_t dstB = sb + CV_B(buf) + tid*32;
        cpa16(dstB,      bsrc,     16);
        cpa16(dstB + 16, bsrc + 2, 16);
        asm volatile("cp.async.commit_group;" ::: "memory");
    };

    stage(0, 0);
    stage(1, 1);

    int bufc = 0;
    for (int s = 0; s < 4; s++) {
        if (s < 3) asm volatile("cp.async.wait_group 1;" ::: "memory");
        else       asm volatile("cp.async.wait_group 0;" ::: "memory");
        __syncthreads();
        int bufn = bufc + 2; if (bufn >= 3) bufn -= 3;
        if (s + 2 < 4) stage(s + 2, bufn);
        const char*  sA = smem + CV_A(bufc);
        const uint2* sB = (const uint2*)(smem + CV_B(bufc));
        #pragma unroll
        for (int h16 = 0; h16 < 2; h16++) {
            uint2 bv[8];
            #pragma unroll
            for (int nt = 0; nt < 8; nt++)
                bv[nt] = sB[(wn*8 + nt)*64 + h16*32 + g*4 + cl];
            uint32_t a[2][4];
            #pragma unroll
            for (int mt = 0; mt < 2; mt++) {
                int r0 = wm*32 + mt*16 + g;
                a[mt][0] = a_word(sA, r0,     h16*8 + cl);
                a[mt][1] = a_word(sA, r0 + 8, h16*8 + cl);
                a[mt][2] = a_word(sA, r0,     h16*8 + cl + 4);
                a[mt][3] = a_word(sA, r0 + 8, h16*8 + cl + 4);
            }
            #pragma unroll
            for (int mt = 0; mt < 2; mt++)
                #pragma unroll
                for (int nt = 0; nt < 8; nt++)
                    mma16(acc[mt][nt][0], acc[mt][nt][1], acc[mt][nt][2], acc[mt][nt][3],
                          a[mt][0], a[mt][1], a[mt][2], a[mt][3],
                          bv[nt].x, bv[nt].y);
        }
        bufc++; if (bufc >= 3) bufc = 0;
    }

    // epilogue: tok = acc + numH*rcp(den) -> g_numH (fp16), plus per-channel partial stats
    float rcp[2][2];
    __half* nb[2][2];
    #pragma unroll
    for (int mt = 0; mt < 2; mt++) {
        int r0 = wm*32 + mt*16 + g;
        int row0 = m0 + r0, row1 = row0 + 8;
        rcp[mt][0] = 1.f/(g_den[row0] + EPSV);
        rcp[mt][1] = 1.f/(g_den[row1] + EPSV);
        nb[mt][0] = g_numH + (size_t)row0*COUT + nh*128;
        nb[mt][1] = g_numH + (size_t)row1*COUT + nh*128;
    }
    #pragma unroll
    for (int nt = 0; nt < 8; nt++) {
        int n = wn*64 + nt*8 + cl*2;
        float s0=0.f, s1=0.f, q0=0.f, q1=0.f;
        #pragma unroll
        for (int mt = 0; mt < 2; mt++) {
            float2 v0 = __half22float2(*(__half2*)(nb[mt][0] + n));
            float2 v1 = __half22float2(*(__half2*)(nb[mt][1] + n));
            float t0 = acc[mt][nt][0] + v0.x*rcp[mt][0];
            float t1 = acc[mt][nt][1] + v0.y*rcp[mt][0];
            float t2 = acc[mt][nt][2] + v1.x*rcp[mt][1];
            float t3 = acc[mt][nt][3] + v1.y*rcp[mt][1];
            *(uint32_t*)(nb[mt][0] + n) = packh2(t0, t1);
            *(uint32_t*)(nb[mt][1] + n) = packh2(t2, t3);
            s0 += t0 + t2; s1 += t1 + t3;
            q0 += t0*t0 + t2*t2; q1 += t1*t1 + t3*t3;
        }
        atomicAdd(&s_sum[n],   s0);
        atomicAdd(&s_sum[n+1], s1);
        atomicAdd(&s_sq[n],    q0);
        atomicAdd(&s_sq[n+1],  q1);
    }
    __syncthreads();
    if (tid < 128) {
        atomicAdd(&g_bnsumF[nh*128 + tid], s_sum[tid]);
        atomicAdd(&g_bnsqF [nh*128 + tid], s_sq[tid]);
    }
}

__global__ void k_bnfinal(const float* __restrict__ gam, const float* __restrict__ bet) {
    int c = threadIdx.x;
    float m  = (float)(BB*NN);
    float mu = g_bnsumF[c]/m;
    float var = g_bnsqF[c]/m - mu*mu;
    float sc = gam[c] * rsqrtf(var + 1e-5f);
    g_scale[c] = sc;
    g_shift[c] = bet[c] - mu*sc;
}

// apply BN on the fly: x_out = relu(bn(tok)), conf, exp(conf). tok read as fp16.
__global__ void k_bnconf(const float* __restrict__ cw, const float* __restrict__ cbv,
                         float* __restrict__ out_xout, float* __restrict__ out_conf) {
    int row  = blockIdx.x*8 + (threadIdx.x>>5);
    int lane = threadIdx.x & 31;
    const uint4* t = (const uint4*)(g_numH + (size_t)row*COUT);
    float4* xo     = (float4*)(out_xout + (size_t)row*COUT);
    uint4 u = t[lane];                      // 8 halves: channels lane*8..+7
    const uint32_t* pu = (const uint32_t*)&u;
    float dot = 0.f;
    #pragma unroll
    for (int q = 0; q < 2; q++) {           // q: group of 4 channels
        int c4 = lane*2 + q;
        float2 h0 = __half22float2(*(__half2*)&pu[2*q]);
        float2 h1 = __half22float2(*(__half2*)&pu[2*q+1]);
        float4 sc = ((const float4*)g_scale)[c4];
        float4 sh = ((const float4*)g_shift)[c4];
        float4 wv = ((const float4*)cw)[c4];
        float4 r = make_float4(h0.x*sc.x+sh.x, h0.y*sc.y+sh.y, h1.x*sc.z+sh.z, h1.y*sc.w+sh.w);
        dot += r.x*wv.x + r.y*wv.y + r.z*wv.z + r.w*wv.w;
        xo[c4] = make_float4(fmaxf(r.x,0.f), fmaxf(r.y,0.f), fmaxf(r.z,0.f), fmaxf(r.w,0.f));
    }
    #pragma unroll
    for (int o = 16; o; o >>= 1) dot += __shfl_xor_sync(0xffffffffu, dot, o);
    if (!lane) {
        float cf = dot + cbv[0];
        out_conf[row] = cf;
        g_wexp[row]   = expf(cf);
    }
}

// gather fp16 tok, apply BN inline, weighted scatter into 64x64 cells
__global__ void k_cluster(const float* __restrict__ loc, const int* __restrict__ idx_agg,
                          float* __restrict__ out_idx) {
    int p    = blockIdx.x*8 + (threadIdx.x>>5);
    int lane = threadIdx.x & 31;
    int b    = p >> 16;
    int cell = grid_cell(loc[2*p], loc[2*p+1], HC, WC);
    int i    = idx_agg[p];
    float w  = g_wexp[(size_t)b*NN + i];
    const uint4* src = (const uint4*)(g_numH + ((size_t)b*NN + i)*COUT);
    float* dst = g_cnum + ((size_t)b*NS + cell)*COUT + lane*8;
    uint4 u = src[lane];
    const uint32_t* pu = (const uint32_t*)&u;
    #pragma unroll
    for (int q = 0; q < 2; q++) {
        int c4 = lane*2 + q;
        float2 h0 = __half22float2(*(__half2*)&pu[2*q]);
        float2 h1 = __half22float2(*(__half2*)&pu[2*q+1]);
        float4 sc = ((const float4*)g_scale)[c4];
        float4 sh = ((const float4*)g_shift)[c4];
        red_add4(dst + q*4, make_float4((h0.x*sc.x+sh.x)*w, (h0.y*sc.y+sh.y)*w,
                                        (h1.x*sc.z+sh.z)*w, (h1.y*sc.w+sh.w)*w));
    }
    if (!lane) {
        atomicAdd(&g_cden[(size_t)b*NS + cell], w);
        g_wpt[p]   = w;
        out_idx[p] = (float)cell;
    }
}

__global__ void k_xdown(float* __restrict__ out_xd) {
    int row  = blockIdx.x*8 + (threadIdx.x>>5);
    int lane = threadIdx.x & 31;
    float rcp = 1.f/(g_cden[row] + EPSV);
    const float4* src = (const float4*)(g_cnum + (size_t)row*COUT);
    float4* dst = (float4*)(out_xd + (size_t)row*COUT);
    #pragma unroll
    for (int q = 0; q < 2; q++) {
        int c4 = q*32 + lane;
        float4 v = src[c4];
        dst[c4] = make_float4(fmaxf(v.x*rcp,0.f), fmaxf(v.y*rcp,0.f),
                              fmaxf(v.z*rcp,0.f), fmaxf(v.w*rcp,0.f));
    }
}

__global__ void k_aggmax(const float* __restrict__ loc, const float* __restrict__ aggw) {
    __shared__ float sm[256];
    int p = blockIdx.x*256 + threadIdx.x;
    int b = p >> 16;
    int cell = grid_cell(loc[2*p], loc[2*p+1], HC, WC);
    float aw = aggw[p] * g_wpt[p] / (g_cden[(size_t)b*NS + cell] + EPSV);
    g_wpt[p] = aw;
    sm[threadIdx.x] = aw;
    __syncthreads();
    for (int s = 128; s; s >>= 1) {
        if (threadIdx.x < s) sm[threadIdx.x] = fmaxf(sm[threadIdx.x], sm[threadIdx.x+s]);
        __syncthreads();
    }
    if (!threadIdx.x) atomicMax(&g_maxw[b], __float_as_uint(sm[0]));
}

__global__ void k_aggnorm(float* __restrict__ out_aw) {
    int p = blockIdx.x*256 + threadIdx.x;
    int b = p >> 16;
    out_aw[p] = g_wpt[p] / __uint_as_float(g_maxw[b]);
}

// ---------------- launch ----------------
extern "C" void kernel_launch(void* const* d_in, const int* in_sizes, int n_in,
                              void* d_out, int out_size) {
    const float* x      = (const float*)d_in[0];
    const float* loc    = (const float*)d_in[1];
    const int*   idxa   = (const int*)  d_in[2];
    const float* aggw   = (const float*)d_in[3];
    const float* conv_w = (const float*)d_in[4];
    const float* conv_b = (const float*)d_in[5];
    const float* skip_w = (const float*)d_in[6];
    const float* gamma  = (const float*)d_in[7];
    const float* beta   = (const float*)d_in[8];
    const float* conf_w = (const float*)d_in[9];
    const float* conf_b = (const float*)d_in[10];

    float* out      = (float*)d_out;
    float* out_xd   = out;                                    // [4,4096,256]
    float* out_xout = out + (size_t)BB*NS*COUT;               // [4,16384,256]
    float* out_conf = out_xout + (size_t)BB*NN*COUT;          // [4,16384,1]
    float* out_aw   = out_conf + (size_t)BB*NN;               // [4,65536,1]
    float* out_idx  = out_aw   + (size_t)BB*NP;               // [4,65536]

    cudaFuncSetAttribute(k_conv, cudaFuncAttributeMaxDynamicSharedMemorySize, CV_SMEM);
    cudaFuncSetAttribute(k_skip, cudaFuncAttributeMaxDynamicSharedMemorySize, CV_SMEM);

    k_init<<<2048, 256>>>(x, skip_w, conv_w);
    k_token2map<<<BB*NP/8, 256>>>(loc, idxa);
    k_norm<<<(BB*HH*WW*CIN/4)/256, 256>>>();
    k_conv<<<dim3(HD, 2, BB), 256, CV_SMEM>>>(conv_b);
    k_map2token<<<BB*NP/8, 256>>>(loc, idxa, aggw);
    k_skip<<<dim3(BB*NN/128, 2), 256, CV_SMEM>>>();
    k_bnfinal<<<1, 256>>>(gamma, beta);
    k_bnconf<<<BB*NN/8, 256>>>(conf_w, conf_b, out_xout, out_conf);
    k_cluster<<<BB*NP/8, 256>>>(loc, idxa, out_idx);
    k_xdown<<<BB*NS/8, 256>>>(out_xd);
    k_aggmax<<<BB*NP/256, 256>>>(loc, aggw);
    k_aggnorm<<<BB*NP/256, 256>>>(out_aw);
}

// round 17
// speedup vs baseline: 1.0323x; 1.0323x over previous
#include <cuda_runtime.h>
#include <cuda_fp16.h>
#include <math.h>
#include <stdint.h>

#define BB   4
#define NN   16384
#define CIN  128
#define COUT 256
#define HH   256
#define WW   256
#define NP   65536      // N0 = H*W points
#define HD   128
#define WD   128
#define HC   64
#define WC   64
#define NS   4096       // HC*WC
#define EPSV 1e-6f
#define KTOT 1152       // 9*CIN
#define SLABS 36        // KTOT/32

// ---------------- scratch (device globals: no allocation allowed) ----------------
__device__ float  g_cnt [(size_t)BB*HH*WW];       // token2map count
__device__ uint2  g_mapH[(size_t)BB*HH*WW*CIN/4]; // fp16 map; after conv reused as v=bn(tok)*w (fp16)
__device__ __half g_yH  [(size_t)BB*HD*WD*COUT];  // conv output fp16 (32MB)
__device__ uint2  g_xH  [(size_t)BB*NN*CIN/4];    // x in fp16 (16MB)
__device__ float  g_num [(size_t)BB*NN*COUT];     // map2token num -> tok (fp32, 64MB)
__device__ float  g_den [(size_t)BB*NN];
__device__ float  g_wexp[(size_t)BB*NN];          // exp(conf)
__device__ float  g_bnsumF[COUT];
__device__ float  g_bnsqF [COUT];
__device__ float  g_scale[COUT];
__device__ float  g_shift[COUT];
__device__ float  g_cnum[(size_t)BB*NS*COUT];     // cluster num (16MB)
__device__ float  g_cden[(size_t)BB*NS];
__device__ float  g_wpt [(size_t)BB*NP];          // per-point weight, reused
__device__ unsigned g_maxw[BB];
__device__ uint2  g_wBh [(size_t)SLABS*2048];     // conv weights fp16 frag image per slab
__device__ uint2  g_wSh [(size_t)4*2048];         // skip weights fp16 frag image (4 slabs)

// ---------------- helpers ----------------
__device__ __forceinline__ void red_add4(float* p, float4 v) {
    asm volatile("red.global.add.v4.f32 [%0], {%1,%2,%3,%4};"
                 :: "l"(__cvta_generic_to_global(p)),
                    "f"(v.x), "f"(v.y), "f"(v.z), "f"(v.w) : "memory");
}

__device__ __forceinline__ int grid_cell(float lx, float ly, int Hg, int Wg) {
    lx = fminf(fmaxf(lx, -1.f), 1.f);
    ly = fminf(fmaxf(ly, -1.f), 1.f);
    int px = min(max(__float2int_rn(0.5f*(lx+1.f)*(float)Wg - 0.5f), 0), Wg-1);
    int py = min(max(__float2int_rn(0.5f*(ly+1.f)*(float)Hg - 0.5f), 0), Hg-1);
    return py*Wg + px;
}

__device__ __forceinline__ uint32_t packh2(float lo, float hi) {
    __half2 h = __floats2half2_rn(lo, hi);
    return *(uint32_t*)&h;
}

__device__ __forceinline__ uint32_t smem_u32(const void* p) {
    uint32_t a;
    asm("{ .reg .u64 t; cvta.to.shared.u64 t, %1; cvt.u32.u64 %0, t; }" : "=r"(a) : "l"(p));
    return a;
}

__device__ __forceinline__ void cpa16(uint32_t dst, const void* src, int srcsz) {
    asm volatile("cp.async.cg.shared.global [%0], [%1], 16, %2;"
                 :: "r"(dst), "l"(__cvta_generic_to_global(src)), "r"(srcsz) : "memory");
}

__device__ __forceinline__ void mma16(float& d0, float& d1, float& d2, float& d3,
                                      uint32_t a0, uint32_t a1, uint32_t a2, uint32_t a3,
                                      uint32_t b0, uint32_t b1) {
    asm volatile("mma.sync.aligned.m16n8k16.row.col.f32.f16.f16.f32 "
                 "{%0,%1,%2,%3},{%4,%5,%6,%7},{%8,%9},{%0,%1,%2,%3};"
                 : "+f"(d0), "+f"(d1), "+f"(d2), "+f"(d3)
                 : "r"(a0), "r"(a1), "r"(a2), "r"(a3), "r"(b0), "r"(b1));
}

__device__ __forceinline__ int aswz(int r, int c) {      // 16B-chunk swizzle
    return c ^ (r & 3) ^ ((r >> 2) & 1);
}
__device__ __forceinline__ uint32_t a_word(const char* sA, int r, int w) {  // w 0..15
    int off = r*64 + aswz(r, w >> 2)*16 + (w & 3)*4;
    return *(const uint32_t*)(sA + off);
}

// ---------------- kernels ----------------
// fused: zero accumulators + fp16 conv/skip B images + fp16 copy of x
__global__ void k_init(const float* __restrict__ x, const float* __restrict__ skw,
                       const float* __restrict__ cw) {
    size_t t = (size_t)blockIdx.x*blockDim.x + threadIdx.x;
    size_t stride = (size_t)gridDim.x*blockDim.x;
    float4 z = make_float4(0.f,0.f,0.f,0.f);
    for (size_t i=t; i < (size_t)BB*HH*WW*CIN/8; i+=stride) ((float4*)g_mapH)[i]=z;
    for (size_t i=t; i < (size_t)BB*HH*WW/4;     i+=stride) ((float4*)g_cnt )[i]=z;
    for (size_t i=t; i < (size_t)BB*NN*COUT/4;   i+=stride) ((float4*)g_num )[i]=z;
    for (size_t i=t; i < (size_t)BB*NN/4;        i+=stride) ((float4*)g_den )[i]=z;
    for (size_t i=t; i < (size_t)BB*NS*COUT/4;   i+=stride) ((float4*)g_cnum)[i]=z;
    for (size_t i=t; i < (size_t)BB*NS/4;        i+=stride) ((float4*)g_cden)[i]=z;
    for (size_t i=t; i < (size_t)BB*NN*CIN/4;    i+=stride) {
        float4 v = ((const float4*)x)[i];
        uint2 h; h.x = packh2(v.x, v.y); h.y = packh2(v.z, v.w);
        g_xH[i] = h;
    }
    if (t < COUT) { g_bnsumF[t]=0.f; g_bnsqF[t]=0.f; }
    if (t < BB)   g_maxw[t]=0u;
    if (t < (size_t)SLABS*2048) {
        int fi = (int)t;
        int s   = fi >> 11, r = fi & 2047;
        int nh  = r >> 10;  int r2 = r & 1023;
        int ntF = r2 >> 6, h16 = (r2 >> 5) & 1, g = (r2 >> 2) & 7, cl = r2 & 3;
        int n   = nh*128 + ntF*8 + g;
        int k0  = s*32 + h16*16 + 2*cl;
        uint2 v;
        v.x = packh2(cw[(size_t)k0*COUT + n],     cw[(size_t)(k0+1)*COUT + n]);
        v.y = packh2(cw[(size_t)(k0+8)*COUT + n], cw[(size_t)(k0+9)*COUT + n]);
        g_wBh[fi] = v;
    }
    if (t < (size_t)4*2048) {
        int fi = (int)t;
        int s   = fi >> 11, r = fi & 2047;
        int nh  = r >> 10;  int r2 = r & 1023;
        int ntF = r2 >> 6, h16 = (r2 >> 5) & 1, g = (r2 >> 2) & 7, cl = r2 & 3;
        int n   = nh*128 + ntF*8 + g;
        int k0  = s*32 + h16*16 + 2*cl;
        const float* wr = skw + (size_t)n*CIN;     // skip_w[n][k]
        uint2 v;
        v.x = packh2(wr[k0],   wr[k0+1]);
        v.y = packh2(wr[k0+8], wr[k0+9]);
        g_wSh[fi] = v;
    }
}

// scatter fp16 token features into fp16 map (sum via f16x2 atomics + count)
__global__ void k_token2map(const float* __restrict__ loc, const int* __restrict__ idx_agg) {
    int p    = blockIdx.x*8 + (threadIdx.x>>5);
    int lane = threadIdx.x & 31;
    int b    = p >> 16;
    float lx = loc[2*p], ly = loc[2*p+1];
    int cell = grid_cell(lx, ly, HH, WW);
    int i    = idx_agg[p];
    uint2 v = g_xH[((size_t)b*NN + i)*CIN/4 + lane];
    __half2* dst = (__half2*)((__half*)g_mapH + ((size_t)b*HH*WW + cell)*CIN + lane*4);
    atomicAdd(dst,     *(__half2*)&v.x);
    atomicAdd(dst + 1, *(__half2*)&v.y);
    if (!lane) atomicAdd(&g_cnt[(size_t)b*HH*WW + cell], 1.0f);
}

// normalize fp16 map in place
__global__ void k_norm() {
    size_t i = (size_t)blockIdx.x*256 + threadIdx.x;
    float rcp = 1.f/(g_cnt[i >> 5] + EPSV);
    uint2 h = g_mapH[i];
    float2 a = __half22float2(*(__half2*)&h.x);
    float2 c = __half22float2(*(__half2*)&h.y);
    uint2 o;
    o.x = packh2(a.x*rcp, a.y*rcp);
    o.y = packh2(c.x*rcp, c.y*rcp);
    g_mapH[i] = o;
}

// ---- 3x3 stride-2 conv as implicit GEMM on mma.sync FP16 (m16n8k16) ----
#define CV_BUF   16384
#define CV_A(i)  ((i)*CV_BUF)
#define CV_B(i)  ((i)*CV_BUF + 8192)
#define CV_BIAS  (3*CV_BUF)
#define CV_SMEM  (CV_BIAS + 1024)

__global__ void __launch_bounds__(256, 2) k_conv(const float* __restrict__ cb) {
    extern __shared__ char smem[];
    uint32_t sb = smem_u32(smem);
    int tid = threadIdx.x, w = tid >> 5, lane = tid & 31;
    int g = lane >> 2, cl = lane & 3;
    int wm = w & 3, wn = w >> 2;                 // warp tile 32m x 64n
    int oy = blockIdx.x, nh = blockIdx.y, b = blockIdx.z;

    if (tid < 128) *(float*)(smem + CV_BIAS + tid*4) = cb[nh*128 + tid];

    float acc[2][8][4];
    #pragma unroll
    for (int mt=0;mt<2;mt++) for (int nt=0;nt<8;nt++) for (int r2=0;r2<4;r2++) acc[mt][nt][r2]=0.f;

    auto stage = [&](int s, int buf) {
        int tap = s >> 2, cinb = (s & 3) * 32;
        int ky = tap / 3, kx = tap - 3*ky;
        int iy = 2*oy - 1 + ky;
        bool iyok = (unsigned)iy < HH;
        int r = tid >> 1, c0 = (tid & 1) * 2;
        int ix = 2*r - 1 + kx;
        bool ok = iyok && ((unsigned)ix < WW);
        const __half* src = (const __half*)g_mapH
            + ((size_t)b*HH*WW + (size_t)(iyok ? iy : 0)*WW + (ok ? ix : 0))*CIN + cinb;
        uint32_t dstA = sb + CV_A(buf) + r*64;
        int sz = ok ? 16 : 0;
        #pragma unroll
        for (int j = 0; j < 2; j++) {
            int c = c0 + j;
            cpa16(dstA + aswz(r, c)*16, src + c*8, sz);
        }
        const uint2* bsrc = g_wBh + (size_t)s*2048 + nh*1024 + tid*4;
        uint32_t dstB = sb + CV_B(buf) + tid*32;
        cpa16(dstB,      bsrc,     16);
        cpa16(dstB + 16, bsrc + 2, 16);
        asm volatile("cp.async.commit_group;" ::: "memory");
    };

    stage(0, 0);
    stage(1, 1);

    int bufc = 0;
    for (int s = 0; s < SLABS; s++) {
        if (s < SLABS-1) asm volatile("cp.async.wait_group 1;" ::: "memory");
        else             asm volatile("cp.async.wait_group 0;" ::: "memory");
        __syncthreads();
        int bufn = bufc + 2; if (bufn >= 3) bufn -= 3;
        if (s + 2 < SLABS) stage(s + 2, bufn);
        const char*  sA = smem + CV_A(bufc);
        const uint2* sB = (const uint2*)(smem + CV_B(bufc));
        #pragma unroll
        for (int h16 = 0; h16 < 2; h16++) {
            uint2 bv[8];
            #pragma unroll
            for (int nt = 0; nt < 8; nt++)
                bv[nt] = sB[(wn*8 + nt)*64 + h16*32 + g*4 + cl];
            uint32_t a[2][4];
            #pragma unroll
            for (int mt = 0; mt < 2; mt++) {
                int r0 = wm*32 + mt*16 + g;
                a[mt][0] = a_word(sA, r0,     h16*8 + cl);
                a[mt][1] = a_word(sA, r0 + 8, h16*8 + cl);
                a[mt][2] = a_word(sA, r0,     h16*8 + cl + 4);
                a[mt][3] = a_word(sA, r0 + 8, h16*8 + cl + 4);
            }
            #pragma unroll
            for (int mt = 0; mt < 2; mt++)
                #pragma unroll
                for (int nt = 0; nt < 8; nt++)
                    mma16(acc[mt][nt][0], acc[mt][nt][1], acc[mt][nt][2], acc[mt][nt][3],
                          a[mt][0], a[mt][1], a[mt][2], a[mt][3],
                          bv[nt].x, bv[nt].y);
        }
        bufc++; if (bufc >= 3) bufc = 0;
    }

    // epilogue: write fp16 y
    const float* bias = (const float*)(smem + CV_BIAS);
    __half* ybase = g_yH + (((size_t)b*HD + oy)*WD)*COUT + nh*128;
    #pragma unroll
    for (int mt = 0; mt < 2; mt++) {
        int ox0 = wm*32 + mt*16 + g;
        #pragma unroll
        for (int nt = 0; nt < 8; nt++) {
            int n = wn*64 + nt*8 + cl*2;
            float b0 = bias[n], b1 = bias[n+1];
            *(uint32_t*)(ybase + (size_t)ox0*COUT + n)     = packh2(acc[mt][nt][0]+b0, acc[mt][nt][1]+b1);
            *(uint32_t*)(ybase + (size_t)(ox0+8)*COUT + n) = packh2(acc[mt][nt][2]+b0, acc[mt][nt][3]+b1);
        }
    }
}

// bilinear gather from fp16 conv map at orig points, weighted scatter to fp32 tokens
__global__ void k_map2token(const float* __restrict__ loc, const int* __restrict__ idx_agg,
                            const float* __restrict__ aggw) {
    int p    = blockIdx.x*8 + (threadIdx.x>>5);
    int lane = threadIdx.x & 31;
    int b    = p >> 16;
    float lx = fminf(fmaxf(loc[2*p],   -1.f), 1.f);
    float ly = fminf(fmaxf(loc[2*p+1], -1.f), 1.f);
    float fx = fminf(fmaxf(0.5f*(lx+1.f)*(float)WD - 0.5f, 0.f), (float)(WD-1));
    float fy = fminf(fmaxf(0.5f*(ly+1.f)*(float)HD - 0.5f, 0.f), (float)(HD-1));
    float x0f = floorf(fx), y0f = floorf(fy);
    float wx = fx - x0f, wy = fy - y0f;
    int x0 = (int)x0f, y0 = (int)y0f;
    int x1 = min(x0+1, WD-1), y1 = min(y0+1, HD-1);
    const __half* base = g_yH + (size_t)b*HD*WD*COUT;
    const uint4* r00 = (const uint4*)(base + (size_t)(y0*WD+x0)*COUT);
    const uint4* r01 = (const uint4*)(base + (size_t)(y0*WD+x1)*COUT);
    const uint4* r10 = (const uint4*)(base + (size_t)(y1*WD+x0)*COUT);
    const uint4* r11 = (const uint4*)(base + (size_t)(y1*WD+x1)*COUT);
    float w00=(1.f-wx)*(1.f-wy), w01=wx*(1.f-wy), w10=(1.f-wx)*wy, w11=wx*wy;
    float wpt = aggw[p];
    int i = idx_agg[p];
    float* dst = g_num + ((size_t)b*NN + i)*COUT + lane*8;
    uint4 ua = r00[lane], ub = r01[lane], uc = r10[lane], ud = r11[lane];
    const uint32_t* pa = (const uint32_t*)&ua;
    const uint32_t* pb = (const uint32_t*)&ub;
    const uint32_t* pc = (const uint32_t*)&uc;
    const uint32_t* pd = (const uint32_t*)&ud;
    #pragma unroll
    for (int q = 0; q < 2; q++) {
        float2 a0 = __half22float2(*(__half2*)&pa[2*q]),   a1 = __half22float2(*(__half2*)&pa[2*q+1]);
        float2 b0 = __half22float2(*(__half2*)&pb[2*q]),   b1 = __half22float2(*(__half2*)&pb[2*q+1]);
        float2 c0 = __half22float2(*(__half2*)&pc[2*q]),   c1 = __half22float2(*(__half2*)&pc[2*q+1]);
        float2 d0 = __half22float2(*(__half2*)&pd[2*q]),   d1 = __half22float2(*(__half2*)&pd[2*q+1]);
        float4 f;
        f.x = (w00*a0.x + w01*b0.x + w10*c0.x + w11*d0.x)*wpt;
        f.y = (w00*a0.y + w01*b0.y + w10*c0.y + w11*d0.y)*wpt;
        f.z = (w00*a1.x + w01*b1.x + w10*c1.x + w11*d1.x)*wpt;
        f.w = (w00*a1.y + w01*b1.y + w10*c1.y + w11*d1.y)*wpt;
        red_add4(dst + q*4, f);
    }
    if (!lane) atomicAdd(&g_den[(size_t)b*NN + i], wpt);
}

// ---- skip GEMM (x @ skip_w^T) on FP16 mma.sync + fused BN partial stats ----
__global__ void __launch_bounds__(256, 2) k_skip() {
    extern __shared__ char smem[];
    uint32_t sb = smem_u32(smem);
    int tid = threadIdx.x, w = tid >> 5, lane = tid & 31;
    int g = lane >> 2, cl = lane & 3;
    int wm = w & 3, wn = w >> 2;
    int m0 = blockIdx.x * 128, nh = blockIdx.y;
    const __half* xrow = (const __half*)g_xH + (size_t)m0*CIN;
    float* s_sum = (float*)(smem + CV_BIAS);        // [128]
    float* s_sq  = (float*)(smem + CV_BIAS + 512);  // [128]

    if (tid < 256) *(float*)(smem + CV_BIAS + tid*4) = 0.f;

    float acc[2][8][4];
    #pragma unroll
    for (int mt=0;mt<2;mt++) for (int nt=0;nt<8;nt++) for (int r2=0;r2<4;r2++) acc[mt][nt][r2]=0.f;

    auto stage = [&](int s, int buf) {
        int r = tid >> 1, c0 = (tid & 1) * 2;
        const __half* src = xrow + (size_t)r*CIN + s*32;
        uint32_t dstA = sb + CV_A(buf) + r*64;
        #pragma unroll
        for (int j = 0; j < 2; j++) {
            int c = c0 + j;
            cpa16(dstA + aswz(r, c)*16, src + c*8, 16);
        }
        const uint2* bsrc = g_wSh + (size_t)s*2048 + nh*1024 + tid*4;
        uint32_t dstB = sb + CV_B(buf) + tid*32;
        cpa16(dstB,      bsrc,     16);
        cpa16(dstB + 16, bsrc + 2, 16);
        asm volatile("cp.async.commit_group;" ::: "memory");
    };

    stage(0, 0);
    stage(1, 1);

    int bufc = 0;
    for (int s = 0; s < 4; s++) {
        if (s < 3) asm volatile("cp.async.wait_group 1;" ::: "memory");
        else       asm volatile("cp.async.wait_group 0;" ::: "memory");
        __syncthreads();
        int bufn = bufc + 2; if (bufn >= 3) bufn -= 3;
        if (s + 2 < 4) stage(s + 2, bufn);
        const char*  sA = smem + CV_A(bufc);
        const uint2* sB = (const uint2*)(smem + CV_B(bufc));
        #pragma unroll
        for (int h16 = 0; h16 < 2; h16++) {
            uint2 bv[8];
            #pragma unroll
            for (int nt = 0; nt < 8; nt++)
                bv[nt] = sB[(wn*8 + nt)*64 + h16*32 + g*4 + cl];
            uint32_t a[2][4];
            #pragma unroll
            for (int mt = 0; mt < 2; mt++) {
                int r0 = wm*32 + mt*16 + g;
                a[mt][0] = a_word(sA, r0,     h16*8 + cl);
                a[mt][1] = a_word(sA, r0 + 8, h16*8 + cl);
                a[mt][2] = a_word(sA, r0,     h16*8 + cl + 4);
                a[mt][3] = a_word(sA, r0 + 8, h16*8 + cl + 4);
            }
            #pragma unroll
            for (int mt = 0; mt < 2; mt++)
                #pragma unroll
                for (int nt = 0; nt < 8; nt++)
                    mma16(acc[mt][nt][0], acc[mt][nt][1], acc[mt][nt][2], acc[mt][nt][3],
                          a[mt][0], a[mt][1], a[mt][2], a[mt][3],
                          bv[nt].x, bv[nt].y);
        }
        bufc++; if (bufc >= 3) bufc = 0;
    }

    // epilogue: tok = acc + num*rcp(den) -> g_num, plus per-channel partial stats
    float rcp[2][2];
    float* nb[2][2];
    #pragma unroll
    for (int mt = 0; mt < 2; mt++) {
        int r0 = wm*32 + mt*16 + g;
        int row0 = m0 + r0, row1 = row0 + 8;
        rcp[mt][0] = 1.f/(g_den[row0] + EPSV);
        rcp[mt][1] = 1.f/(g_den[row1] + EPSV);
        nb[mt][0] = g_num + (size_t)row0*COUT + nh*128;
        nb[mt][1] = g_num + (size_t)row1*COUT + nh*128;
    }
    #pragma unroll
    for (int nt = 0; nt < 8; nt++) {
        int n = wn*64 + nt*8 + cl*2;
        float s0=0.f, s1=0.f, q0=0.f, q1=0.f;
        #pragma unroll
        for (int mt = 0; mt < 2; mt++) {
            float2 v0 = *(float2*)(nb[mt][0] + n);
            float2 v1 = *(float2*)(nb[mt][1] + n);
            float t0 = acc[mt][nt][0] + v0.x*rcp[mt][0];
            float t1 = acc[mt][nt][1] + v0.y*rcp[mt][0];
            float t2 = acc[mt][nt][2] + v1.x*rcp[mt][1];
            float t3 = acc[mt][nt][3] + v1.y*rcp[mt][1];
            *(float2*)(nb[mt][0] + n) = make_float2(t0, t1);
            *(float2*)(nb[mt][1] + n) = make_float2(t2, t3);
            s0 += t0 + t2; s1 += t1 + t3;
            q0 += t0*t0 + t2*t2; q1 += t1*t1 + t3*t3;
        }
        atomicAdd(&s_sum[n],   s0);
        atomicAdd(&s_sum[n+1], s1);
        atomicAdd(&s_sq[n],    q0);
        atomicAdd(&s_sq[n+1],  q1);
    }
    __syncthreads();
    if (tid < 128) {
        atomicAdd(&g_bnsumF[nh*128 + tid], s_sum[tid]);
        atomicAdd(&g_bnsqF [nh*128 + tid], s_sq[tid]);
    }
}

__global__ void k_bnfinal(const float* __restrict__ gam, const float* __restrict__ bet) {
    int c = threadIdx.x;
    float m  = (float)(BB*NN);
    float mu = g_bnsumF[c]/m;
    float var = g_bnsqF[c]/m - mu*mu;
    float sc = gam[c] * rsqrtf(var + 1e-5f);
    g_scale[c] = sc;
    g_shift[c] = bet[c] - mu*sc;
}

// apply BN: x_out = relu(bn(tok)), conf, exp(conf); ALSO store v = bn(tok)*exp(conf)
// as fp16 into retired g_mapH buffer for k_cluster.
__global__ void k_bnconf(const float* __restrict__ cw, const float* __restrict__ cbv,
                         float* __restrict__ out_xout, float* __restrict__ out_conf) {
    int row  = blockIdx.x*8 + (threadIdx.x>>5);
    int lane = threadIdx.x & 31;
    const float4* t  = (const float4*)(g_num  + (size_t)row*COUT);
    float4* xo       = (float4*)(out_xout + (size_t)row*COUT);
    float4 r4[2];
    float dot = 0.f;
    #pragma unroll
    for (int q = 0; q < 2; q++) {
        int c4 = q*32 + lane;
        float4 v  = t[c4];
        float4 sc = ((const float4*)g_scale)[c4];
        float4 sh = ((const float4*)g_shift)[c4];
        float4 w  = ((const float4*)cw)[c4];
        float4 r = make_float4(v.x*sc.x+sh.x, v.y*sc.y+sh.y, v.z*sc.z+sh.z, v.w*sc.w+sh.w);
        r4[q] = r;
        dot += r.x*w.x + r.y*w.y + r.z*w.z + r.w*w.w;
        xo[c4] = make_float4(fmaxf(r.x,0.f), fmaxf(r.y,0.f), fmaxf(r.z,0.f), fmaxf(r.w,0.f));
    }
    #pragma unroll
    for (int o = 16; o; o >>= 1) dot += __shfl_xor_sync(0xffffffffu, dot, o);
    float cf = dot + cbv[0];
    float wv = expf(cf);
    if (!lane) {
        out_conf[row] = cf;
        g_wexp[row]   = wv;
    }
    __half* vH = (__half*)g_mapH + (size_t)row*COUT;
    #pragma unroll
    for (int q = 0; q < 2; q++) {
        int c4 = q*32 + lane;
        *(uint32_t*)(vH + c4*4)     = packh2(r4[q].x*wv, r4[q].y*wv);
        *(uint32_t*)(vH + c4*4 + 2) = packh2(r4[q].z*wv, r4[q].w*wv);
    }
}

// gather precomputed fp16 v = bn(tok)*w, scatter into 64x64 cells (fp32 red)
__global__ void k_cluster(const float* __restrict__ loc, const int* __restrict__ idx_agg,
                          float* __restrict__ out_idx) {
    int p    = blockIdx.x*8 + (threadIdx.x>>5);
    int lane = threadIdx.x & 31;
    int b    = p >> 16;
    int cell = grid_cell(loc[2*p], loc[2*p+1], HC, WC);
    int i    = idx_agg[p];
    float w  = g_wexp[(size_t)b*NN + i];
    const uint4* src = (const uint4*)((const __half*)g_mapH + ((size_t)b*NN + i)*COUT);
    float* dst = g_cnum + ((size_t)b*NS + cell)*COUT + lane*8;
    uint4 u = src[lane];
    const uint32_t* pu = (const uint32_t*)&u;
    #pragma unroll
    for (int q = 0; q < 2; q++) {
        float2 h0 = __half22float2(*(__half2*)&pu[2*q]);
        float2 h1 = __half22float2(*(__half2*)&pu[2*q+1]);
        red_add4(dst + q*4, make_float4(h0.x, h0.y, h1.x, h1.y));
    }
    if (!lane) {
        atomicAdd(&g_cden[(size_t)b*NS + cell], w);
        g_wpt[p]   = w;
        out_idx[p] = (float)cell;
    }
}

__global__ void k_xdown(float* __restrict__ out_xd) {
    int row  = blockIdx.x*8 + (threadIdx.x>>5);
    int lane = threadIdx.x & 31;
    float rcp = 1.f/(g_cden[row] + EPSV);
    const float4* src = (const float4*)(g_cnum + (size_t)row*COUT);
    float4* dst = (float4*)(out_xd + (size_t)row*COUT);
    #pragma unroll
    for (int q = 0; q < 2; q++) {
        int c4 = q*32 + lane;
        float4 v = src[c4];
        dst[c4] = make_float4(fmaxf(v.x*rcp,0.f), fmaxf(v.y*rcp,0.f),
                              fmaxf(v.z*rcp,0.f), fmaxf(v.w*rcp,0.f));
    }
}

__global__ void k_aggmax(const float* __restrict__ loc, const float* __restrict__ aggw) {
    __shared__ float sm[256];
    int p = blockIdx.x*256 + threadIdx.x;
    int b = p >> 16;
    int cell = grid_cell(loc[2*p], loc[2*p+1], HC, WC);
    float aw = aggw[p] * g_wpt[p] / (g_cden[(size_t)b*NS + cell] + EPSV);
    g_wpt[p] = aw;
    sm[threadIdx.x] = aw;
    __syncthreads();
    for (int s = 128; s; s >>= 1) {
        if (threadIdx.x < s) sm[threadIdx.x] = fmaxf(sm[threadIdx.x], sm[threadIdx.x+s]);
        __syncthreads();
    }
    if (!threadIdx.x) atomicMax(&g_maxw[b], __float_as_uint(sm[0]));
}

__global__ void k_aggnorm(float* __restrict__ out_aw) {
    int p = blockIdx.x*256 + threadIdx.x;
    int b = p >> 16;
    out_aw[p] = g_wpt[p] / __uint_as_float(g_maxw[b]);
}

// ---------------- launch ----------------
extern "C" void kernel_launch(void* const* d_in, const int* in_sizes, int n_in,
                              void* d_out, int out_size) {
    const float* x      = (const float*)d_in[0];
    const float* loc    = (const float*)d_in[1];
    const int*   idxa   = (const int*)  d_in[2];
    const float* aggw   = (const float*)d_in[3];
    const float* conv_w = (const float*)d_in[4];
    const float* conv_b = (const float*)d_in[5];
    const float* skip_w = (const float*)d_in[6];
    const float* gamma  = (const float*)d_in[7];
    const float* beta   = (const float*)d_in[8];
    const float* conf_w = (const float*)d_in[9];
    const float* conf_b = (const float*)d_in[10];

    float* out      = (float*)d_out;
    float* out_xd   = out;                                    // [4,4096,256]
    float* out_xout = out + (size_t)BB*NS*COUT;               // [4,16384,256]
    float* out_conf = out_xout + (size_t)BB*NN*COUT;          // [4,16384,1]
    float* out_aw   = out_conf + (size_t)BB*NN;               // [4,65536,1]
    float* out_idx  = out_aw   + (size_t)BB*NP;               // [4,65536]

    cudaFuncSetAttribute(k_conv, cudaFuncAttributeMaxDynamicSharedMemorySize, CV_SMEM);
    cudaFuncSetAttribute(k_skip, cudaFuncAttributeMaxDynamicSharedMemorySize, CV_SMEM);

    k_init<<<2048, 256>>>(x, skip_w, conv_w);
    k_token2map<<<BB*NP/8, 256>>>(loc, idxa);
    k_norm<<<(BB*HH*WW*CIN/4)/256, 256>>>();
    k_conv<<<dim3(HD, 2, BB), 256, CV_SMEM>>>(conv_b);
    k_map2token<<<BB*NP/8, 256>>>(loc, idxa, aggw);
    k_skip<<<dim3(BB*NN/128, 2), 256, CV_SMEM>>>();
    k_bnfinal<<<1, 256>>>(gamma, beta);
    k_bnconf<<<BB*NN/8, 256>>>(conf_w, conf_b, out_xout, out_conf);
    k_cluster<<<BB*NP/8, 256>>>(loc, idxa, out_idx);
    k_xdown<<<BB*NS/8, 256>>>(out_xd);
    k_aggmax<<<BB*NP/256, 256>>>(loc, aggw);
    k_aggnorm<<<BB*NP/256, 256>>>(out_aw);
}